// round 14
// baseline (speedup 1.0000x reference)
#include <cuda_runtime.h>
#include <math.h>

#define BB 4
#define TT 336
#define NN 862
#define DD 64
#define RR 8
#define KK 6
#define PP 96
#define NBMAX 8
#define NBD 9       // max boundary entries (nb+1)
#define CH 32
#define NCH 27      // ceil(862/32)
#define NT2 12      // k_gemm rows per block
#define GT2 72      // ceil(862/12)
#define GW 192      // G12 row width in floats (PP*2)

// ---------------- device scratch ----------------
__device__ float g_xbar[BB*NN];
__device__ float g_xT[BB*NN*TT];
__device__ float g_xsorted[BB*NN];
__device__ int   g_sid[BB*NN];
__device__ float g_U12[TT*PP*2];          // interleaved (u1,u2)
__device__ float g_G12[BB*NN*GW];         // G = XT @ U12, interleaved, 192 f/row
__device__ float g_PUl[BB*NN*GW];         // chunk-local prefixes of G in sorted order
__device__ float g_PUtot[BB*NCH*GW];      // chunk totals
__device__ float g_Sdp[DD*PP];
__device__ float g_constP[PP];
__device__ float g_cwP[PP];
__device__ float g_sgate[1];
__device__ double g_cA, g_cG, g_cA2, g_cG2;
__device__ float g_c0[DD];
__device__ float g_v[DD];
__device__ float g_w[DD];
__device__ float g_dinv[NN];
__device__ float g_rA[NN];
__device__ int   g_csr_cnt[NN];
__device__ int   g_csr_col[NN*NN];
__device__ float g_csr_val[NN*NN];
__device__ int   g_nbd[BB*NN];
__device__ float g_bc[BB*NN*NBD];
__device__ int   g_be[BB*NN*NBD];         // sorted-position index e-1 (0..NN-1)
__device__ float g_O1[BB*NN*PP];
__device__ float g_O2[BB*NN*PP];

__device__ __forceinline__ float warp_sum(float v) {
    for (int o = 16; o; o >>= 1) v += __shfl_down_sync(0xffffffffu, v, o);
    return v;
}
__device__ __forceinline__ int warp_isum(int v) {
    for (int o = 16; o; o >>= 1) v += __shfl_down_sync(0xffffffffu, v, o);
    return v;
}

// ---------- double-float (Dekker) helpers ----------
struct dfloat { float hi, lo; };
__device__ __forceinline__ dfloat df_two_sum(float a, float b) {
    float s = a + b;
    float bb = s - a;
    float err = (a - (s - bb)) + (b - bb);
    return {s, err};
}
__device__ __forceinline__ dfloat df_two_prod(float a, float b) {
    float p = a * b;
    float e = fmaf(a, b, -p);
    return {p, e};
}
__device__ __forceinline__ dfloat df_mul_f(dfloat a, float b) {
    dfloat p = df_two_prod(a.hi, b);
    p.lo = fmaf(a.lo, b, p.lo);
    return df_two_sum(p.hi, p.lo);
}
__device__ __forceinline__ dfloat df_add_f(dfloat a, float b) {
    dfloat s = df_two_sum(a.hi, b);
    s.lo += a.lo;
    return df_two_sum(s.hi, s.lo);
}

// fl32-faithful exp for our regime
__device__ __forceinline__ float exp_f32cr(float d) {
    if (d > -0.001f && d <= 0.001f) {
        dfloat r = {0.16666667f, -4.9670537e-9f};  // df(1/6)
        r = df_mul_f(r, d);
        r = df_add_f(r, 0.5f);
        r = df_mul_f(r, d);
        r = df_add_f(r, 1.0f);
        r = df_mul_f(r, d);
        r = df_add_f(r, 1.0f);
        return r.hi + r.lo;
    }
    return (float)exp((double)d);
}

// ================= stage 1: transpose + xbar + deg + scalars + S =================
#define S1_TP   1188   // 27*11*4
#define S1_XB   (S1_TP + 14)
#define S1_DEG  (S1_XB + 108)
#define S1_SCAL (S1_DEG + 1)
#define S1_S    (S1_SCAL + 24)

__global__ void k_stage1(const float* __restrict__ x, const float* __restrict__ We,
                         const float* __restrict__ be, const float* __restrict__ W1,
                         const float* __restrict__ W2, const float* __restrict__ gate,
                         const float* __restrict__ Apr, const float* __restrict__ Wg,
                         const float* __restrict__ Wh) {
    __shared__ float sh[1088];
    int blk = blockIdx.x;
    int tid = threadIdx.x; // 256

    if (blk < S1_TP) {
        int bz = blk / (27*11);
        int rem = blk % (27*11);
        int tn = rem % 27, tt2 = rem / 27;
        int lx = tid & 31, ly = tid >> 5; // 8 rows
        #pragma unroll
        for (int r = 0; r < 32; r += 8) {
            int n = tn*32 + lx, t = tt2*32 + ly + r;
            if (n < NN && t < TT) sh[(ly+r)*33 + lx] = x[(bz*TT + t)*NN + n];
        }
        __syncthreads();
        #pragma unroll
        for (int r = 0; r < 32; r += 8) {
            int n2 = tn*32 + ly + r, t2 = tt2*32 + lx;
            if (n2 < NN && t2 < TT) g_xT[(bz*NN + n2)*TT + t2] = sh[lx*33 + (ly+r)];
        }
    } else if (blk < S1_XB) {
        int idx = (blk - S1_TP)*256 + tid;
        if (idx < BB*NN) {
            int b = idx / NN, n = idx % NN;
            float s = 0;
            for (int t = 0; t < TT; t++) s += x[(b*TT + t)*NN + n];
            g_xbar[idx] = s * (1.f / TT);
        }
    } else if (blk < S1_DEG) {
        int w = (blk - S1_XB)*8 + (tid >> 5);
        int lane = tid & 31;
        if (w < NN) {
            float s = 0;
            for (int m = lane; m < NN; m += 32) s += Apr[w*NN + m];
            s = warp_sum(s);
            if (lane == 0) g_dinv[w] = (s > 0.f) ? (1.f / sqrtf(s)) : 0.f;
        }
    } else if (blk < S1_SCAL) {
        double* da = (double*)sh;
        float s = 1.f / (1.f + expf(-gate[0]));
        if (tid < RR) {
            double s1 = 0, s2 = 0, s3 = 0, s4 = 0;
            for (int d = 0; d < DD; d++) {
                double w1 = W1[d*RR + tid], w2 = W2[d*RR + tid];
                double we = We[d], beq = be[d];
                s1 += we*w1; s2 += beq*w1; s3 += we*w2; s4 += beq*w2;
            }
            da[tid] = s1; da[8+tid] = s2; da[16+tid] = s3; da[24+tid] = s4;
        }
        if (tid < DD) {
            float vv = 0, ww = 0;
            for (int d = 0; d < DD; d++) {
                float wg = Wg[d*DD + tid];
                vv += We[d]*wg;
                ww += (1.f + s)*be[d]*wg;
            }
            g_v[tid] = vv; g_w[tid] = ww; g_c0[tid] = (1.f + s)*be[tid];
        }
        __syncthreads();
        if (tid == 0) {
            double A = 0, G = 0, A2 = 0, G2 = 0;
            for (int r = 0; r < RR; r++) {
                A += da[r]*da[16+r]; G += da[8+r]*da[16+r];
                A2 += da[r]*da[24+r]; G2 += da[8+r]*da[24+r];
            }
            double inv = 1.0 / sqrt(8.0);
            g_cA = A*inv; g_cG = G*inv; g_cA2 = A2*inv; g_cG2 = G2*inv;
            g_sgate[0] = s;
        }
    } else {
        int idx = (blk - S1_SCAL)*256 + tid;
        if (idx < DD*PP) {
            int d = idx / PP, p = idx % PP;
            float s = 0;
            for (int t = 0; t < TT; t++) s += Wh[((size_t)t*DD + d)*PP + p];
            g_Sdp[idx] = s;
        }
    }
}

// ================= stage 2: sort + csr + U + cp =================
#define S2_SORT 108                  // 4 batches * 27 groups of 32 rows
#define S2_CSR  (S2_SORT + 108)
#define S2_U    (S2_CSR + 126)
#define S2_CP   (S2_U + 1)

__global__ void k_stage2(const float* __restrict__ Apr, const float* __restrict__ We,
                         const float* __restrict__ Wh, const float* __restrict__ bh) {
    __shared__ float sh[1088];
    int blk = blockIdx.x;
    int tid = threadIdx.x; // 256

    if (blk < S2_SORT) {
        int b = blk / 27;
        int mg = blk % 27;
        for (int i = tid; i < NN; i += 256) sh[i] = g_xbar[b*NN + i];
        __syncthreads();
        int w = tid >> 5, lane = tid & 31;
        #pragma unroll
        for (int k = 0; k < 4; k++) {
            int m = mg*32 + w*4 + k;
            if (m < NN) {
                float v = sh[m];
                int r = 0;
                for (int j = lane; j < NN; j += 32) {
                    float u = sh[j];
                    r += (u > v) || (u == v && j < m);
                }
                r = warp_isum(r);
                if (lane == 0) { g_sid[b*NN + r] = m; g_xsorted[b*NN + r] = v; }
            }
        }
    } else if (blk < S2_CSR) {
        int n = (blk - S2_SORT)*8 + (tid >> 5);
        int lane = tid & 31;
        if (n < NN) {
            float dn = g_dinv[n];
            int base = 0; float rsum = 0;
            for (int m0 = 0; m0 < NN; m0 += 32) {
                int m = m0 + lane;
                float v = 0;
                if (m < NN) v = Apr[n*NN + m] * dn * g_dinv[m];
                unsigned mask = __ballot_sync(0xffffffffu, v != 0.f);
                if (v != 0.f) {
                    int pos = base + __popc(mask & ((1u << lane) - 1u));
                    g_csr_col[n*NN + pos] = m;
                    g_csr_val[n*NN + pos] = v;
                }
                base += __popc(mask);
                float cs = warp_sum(v);
                if (lane == 0) rsum += cs;
            }
            if (lane == 0) { g_csr_cnt[n] = base; g_rA[n] = rsum; }
        }
    } else if (blk < S2_U) {
        int idx = (blk - S2_CSR)*256 + tid;
        if (idx < TT*PP) {
            int t = idx / PP, p = idx % PP;
            float u1 = 0, u2 = 0;
            const float* basep = Wh + (size_t)t*DD*PP;
            for (int d = 0; d < DD; d++) {
                float w = basep[d*PP + p];
                u1 += We[d]*w; u2 += g_v[d]*w;
            }
            g_U12[idx*2] = u1; g_U12[idx*2 + 1] = u2;
        }
    } else {
        int p = tid;
        if (p < PP) {
            float c = 0, cw = 0;
            for (int d = 0; d < DD; d++) {
                float sdp = g_Sdp[d*PP + p];
                c += g_c0[d]*sdp; cw += g_w[d]*sdp;
            }
            g_constP[p] = c + bh[p];
            g_cwP[p] = cw;
        }
    }
}

// ================= stage 3: selection only =================
__global__ void k_stage3() {
    __shared__ float sh[1088];
    int blk = blockIdx.x;   // 16 blocks
    int tid = threadIdx.x;  // 256
    int b = blk >> 2, sub = blk & 3;
    for (int m = tid; m < NN; m += 256) sh[m] = g_xsorted[b*NN + m];
    __syncthreads();
    int n = sub*256 + tid;
    if (n >= NN) return;
    int gw = b*NN + n;

    double xn = (double)g_xbar[gw];
    double pd = g_cA*xn + g_cG;
    double qd = g_cA2*xn + g_cG2;
    int dir = (pd < 0.0);
    float phi = (float)pd, plo = (float)(pd - (double)phi);
    float qhi = (float)qd, qlo = (float)(qd - (double)qhi);

    auto EV = [&](int j) -> float {
        int sj = dir ? (NN-1-j) : j;
        float xv = sh[sj];
        dfloat t = df_two_prod(phi, xv);
        t.lo = fmaf(plo, xv, t.lo);
        dfloat s = df_two_sum(t.hi, qhi);
        s.lo += t.lo + qlo;
        return s.hi + s.lo;   // fl32(p*x+q)
    };

    float l0 = EV(0), lN = EV(NN-1);
    float lmax = fmaxf(l0, lN);

    float be_[16]; int bst[16];
    int nbk = 0, pos = 0, stored_end = 0, nwalk = 0;
    double Zd = 0.0;
    bool fb = false;
    while (pos < NN) {
        float v = exp_f32cr(EV(pos) - lmax);
        int lo = pos, hi = NN - 1;
        while (lo < hi) {
            int mid = (lo + hi + 1) >> 1;
            if (exp_f32cr(EV(mid) - lmax) == v) lo = mid; else hi = mid - 1;
        }
        int end = lo + 1;
        Zd += (double)v * (double)(end - pos);
        if (nbk < 16) { be_[nbk] = v; bst[nbk] = pos; nbk++; stored_end = end; }
        pos = end;
        if (++nwalk > 96) { if (pos < NN) fb = true; break; }
    }

    float tval[NBMAX]; int tlo[NBMAX];
    int nb = 0, J = NN;

    if (!fb) {
        float Zf = (float)Zd;
        int ti = 0;
        while (ti + 1 < nbk && bst[ti+1] <= KK-1) ti++;
        float thresh = __fdiv_rn(be_[ti], Zf);
        bool done = false;
        for (int k = 0; k < nbk && !done; k++) {
            float adj = __fdiv_rn(be_[k], Zf);
            if (adj >= thresh) {
                if (nb == 0 || adj != tval[nb-1]) {
                    if (nb < NBMAX) { tval[nb] = adj; tlo[nb] = bst[k]; nb++; }
                }
            } else { J = bst[k]; done = true; }
        }
        if (!done) {
            if (nbk == 16 && stored_end < NN) fb = true;
            else J = NN;
        }
    }

    if (fb) {
        double Zd2 = 0;
        for (int j = 0; j < NN; j++) Zd2 += (double)exp_f32cr(EV(j) - lmax);
        float Zf2 = (float)Zd2;
        float thresh = __fdiv_rn(exp_f32cr(EV(KK-1) - lmax), Zf2);
        nb = 0; J = NN;
        for (int j = 0; j < NN; j++) {
            float adj = __fdiv_rn(exp_f32cr(EV(j) - lmax), Zf2);
            if (!(adj >= thresh)) { J = j; break; }
            if (nb == 0 || adj != tval[nb-1]) {
                if (nb < NBMAX) { tval[nb] = adj; tlo[nb] = j; nb++; }
            }
        }
    }

    double den = 0;
    for (int i = 0; i < nb; i++) {
        int hi = (i+1 < nb) ? tlo[i+1] : J;
        den += (double)tval[i] * (double)(hi - tlo[i]);
    }
    if (den < 1e-12) den = 1e-12;
    float sfac = g_sgate[0] * (float)(1.0/den);

    // boundary-form coefficients: mix(p) = sum_j bc[j] * PU[e_j - 1, p]
    int nbd = 0;
    float bc[NBD]; int bidx[NBD];
    if (!dir) {
        for (int j = 1; j < nb; j++) {
            int e = tlo[j];
            float c = (tval[j-1] - tval[j]) * sfac;
            if (e > 0) { bidx[nbd] = e; bc[nbd] = c; nbd++; }
        }
        if (J > 0) { bidx[nbd] = J; bc[nbd] = tval[nb-1] * sfac; nbd++; }
    } else {
        { bidx[nbd] = NN; bc[nbd] = tval[0] * sfac; nbd++; }
        for (int j = 1; j < nb; j++) {
            int e = NN - tlo[j];
            float c = (tval[j] - tval[j-1]) * sfac;
            if (e > 0) { bidx[nbd] = e; bc[nbd] = c; nbd++; }
        }
        { int e = NN - J; if (e > 0) { bidx[nbd] = e; bc[nbd] = -tval[nb-1] * sfac; nbd++; } }
    }
    g_nbd[gw] = nbd;
    for (int j = 0; j < nbd; j++) {
        g_bc[gw*NBD + j] = bc[j];
        g_be[gw*NBD + j] = bidx[j] - 1;     // sorted-position index
    }
}

// ================= k_gemm: G12 = XT @ U12 (U staged in smem) =================
// grid (GT2, BB), 384 threads: 12 rows x full K=336 in 8 half-chunks of 42.
__global__ void __launch_bounds__(384) k_gemm() {
    __shared__ __align__(16) float Us[42*PP*2];   // 32256B
    __shared__ __align__(16) float xs[42*16];     // 2688B: 12 rows as 4 groups of 3 (+pad)
    int tid = threadIdx.x;
    int p = tid % PP;
    int rg = tid / PP;      // 0..3, 3 rows each; warps never straddle rg
    int n0 = blockIdx.x*NT2;
    int b = blockIdx.y;
    int nrows = min(NT2, NN - n0);

    // zero pad slot 3 of each group (never written later)
    for (int idx = tid; idx < 42*4; idx += 384)
        xs[(idx>>2)*16 + (idx&3)*4 + 3] = 0.f;

    float acc1[3] = {0,0,0}, acc2[3] = {0,0,0};
    const float2* Usrc2 = (const float2*)g_U12;
    float2* Us2 = (float2*)Us;

    for (int h = 0; h < 8; h++) {
        __syncthreads();
        for (int k2 = tid; k2 < 42*96; k2 += 384)
            Us2[k2] = Usrc2[h*4032 + k2];
        for (int idx = tid; idx < NT2*42; idx += 384) {
            int r = idx / 42, tt = idx - r*42;
            float v = 0.f;
            if (r < nrows)
                v = g_xT[(b*NN + n0 + r)*TT + h*42 + tt];
            xs[tt*16 + (r/3)*4 + (r - (r/3)*3)] = v;
        }
        __syncthreads();
        #pragma unroll 6
        for (int ttl = 0; ttl < 42; ttl++) {
            float2 u = Us2[ttl*96 + p];
            float4 a = *(const float4*)&xs[ttl*16 + rg*4];
            acc1[0] += a.x*u.x;  acc2[0] += a.x*u.y;
            acc1[1] += a.y*u.x;  acc2[1] += a.y*u.y;
            acc1[2] += a.z*u.x;  acc2[2] += a.z*u.y;
        }
    }
    float2* Gout = (float2*)g_G12;
    #pragma unroll
    for (int i = 0; i < 3; i++) {
        int r = rg*3 + i;
        if (r < nrows)
            Gout[(b*NN + n0 + r)*PP + p] = make_float2(acc1[i], acc2[i]);  // 96 f2/row
    }
}

// ================= k_pu: chunk-local prefix of G12 in sorted order ===========
// grid (NCH, BB), 192 threads: one float lane each (row = 192 floats).
__global__ void k_pu() {
    int ch = blockIdx.x, b = blockIdx.y;
    int k = threadIdx.x;   // 192
    int j0 = ch*CH, j1 = min(j0 + CH, NN);
    __shared__ int ssid[CH];
    if (k < j1 - j0) ssid[k] = g_sid[b*NN + j0 + k];
    __syncthreads();
    float acc = 0;
    for (int j = j0; j < j1; j++) {
        acc += g_G12[(b*NN + ssid[j - j0])*GW + k];
        g_PUl[(b*NN + j)*GW + k] = acc;
    }
    g_PUtot[(b*NCH + ch)*GW + k] = acc;
}

// ================= k_mix: O = G + boundary-weighted PU lookups ===============
// grid (108, BB), 192 threads; 8 rows per block; chunk offsets staged in smem.
__global__ void __launch_bounds__(192) k_mix() {
    __shared__ float sOff[NCH*GW];      // 20736B
    __shared__ float sbc[8][NBD];
    __shared__ int   sbe[8][NBD];
    __shared__ int   snbd[8];
    int k = threadIdx.x;     // 0..191
    int p = k >> 1, s = k & 1;
    int b = blockIdx.y;
    int n0 = blockIdx.x*8;

    // per-(b,k) chunk offsets (exclusive prefix of chunk totals)
    {
        float off = 0;
        const float* tot = &g_PUtot[b*NCH*GW + k];
        #pragma unroll
        for (int cc = 0; cc < NCH; cc++) {
            sOff[cc*GW + k] = off;
            off += tot[cc*GW];
        }
    }
    if (k < 8) {
        int n = n0 + k;
        int ok = (n < NN);
        int id = b*NN + (ok ? n : 0);
        int nd = ok ? g_nbd[id] : 0; if (nd > NBD) nd = NBD;
        snbd[k] = nd;
        for (int j = 0; j < NBD; j++) {
            sbc[k][j] = g_bc[id*NBD + j];
            sbe[k][j] = g_be[id*NBD + j];
        }
    }
    __syncthreads();

    for (int i = 0; i < 8; i++) {
        int n = n0 + i;
        if (n >= NN) break;
        float mix = 0;
        int nd = snbd[i];
        for (int j = 0; j < nd; j++) {
            int e = sbe[i][j];
            float pu = g_PUl[(b*NN + e)*GW + k] + sOff[(e >> 5)*GW + k];
            mix += sbc[i][j] * pu;
        }
        float o = g_G12[(b*NN + n)*GW + k] + mix;
        if (s == 0) g_O1[(b*NN + n)*PP + p] = o;
        else        g_O2[(b*NN + n)*PP + p] = o;
    }
}

// ================= k_fin: out = O1 + g*A_hat@O2 + consts =================
__global__ void k_fin(const float* __restrict__ ggp, float* __restrict__ out) {
    int b = blockIdx.y;
    int n = blockIdx.x*32 + threadIdx.x;
    if (n >= NN) return;
    float gg = ggp[0];
    int cnt = g_csr_cnt[n];
    float rterm = gg * g_rA[n];
    for (int p = threadIdx.y; p < PP; p += 8) {
        float acc = 0;
        for (int k = 0; k < cnt; k++)
            acc += g_csr_val[n*NN + k] * g_O2[(b*NN + g_csr_col[n*NN + k])*PP + p];
        out[((size_t)b*PP + p)*NN + n] =
            g_O1[(b*NN + n)*PP + p] + gg*acc + g_constP[p] + rterm*g_cwP[p];
    }
}

// ---------------- launcher ----------------
extern "C" void kernel_launch(void* const* d_in, const int* in_sizes, int n_in,
                              void* d_out, int out_size) {
    const float* x    = (const float*)d_in[0];
    const float* We   = (const float*)d_in[1];
    const float* be   = (const float*)d_in[2];
    const float* W1   = (const float*)d_in[3];
    const float* W2   = (const float*)d_in[4];
    const float* gate = (const float*)d_in[5];
    const float* Apr  = (const float*)d_in[6];
    const float* Wg   = (const float*)d_in[7];
    const float* ggcn = (const float*)d_in[8];
    const float* Wh   = (const float*)d_in[9];
    const float* bh   = (const float*)d_in[10];
    float* out = (float*)d_out;

    k_stage1<<<S1_S, 256>>>(x, We, be, W1, W2, gate, Apr, Wg, Wh);
    k_stage2<<<S2_CP, 256>>>(Apr, We, Wh, bh);
    k_stage3<<<16, 256>>>();
    k_gemm<<<dim3(GT2, BB), 384>>>();
    k_pu<<<dim3(NCH, BB), 192>>>();
    k_mix<<<dim3((NN + 7)/8, BB), 192>>>();
    k_fin<<<dim3((NN + 31)/32, BB), dim3(32, 8)>>>(ggcn, out);
}